// round 11
// baseline (speedup 1.0000x reference)
#include <cuda_runtime.h>
#include <cuda_bf16.h>
#include <cfloat>
#include <cstdint>

#define HIDDEN    1024
#define NUM_HEADS 16
#define HEAD_DIM  64
#define BATCH     32
#define PREV_LEN  4095
#define SEQ       4096
#define SCALING   0.125f

__device__ float g_q[BATCH * HIDDEN];
__device__ float g_k[BATCH * HIDDEN];
__device__ float g_v[BATCH * HIDDEN];
// unnormalized attention partials over the 4095 cached positions
__device__ float g_fm[BATCH * NUM_HEADS];
__device__ float g_fl[BATCH * NUM_HEADS];
__device__ float g_facc[BATCH * NUM_HEADS * HEAD_DIM];

__device__ __forceinline__ float dot4(float4 a, float4 b) {
    return a.x*b.x + a.y*b.y + a.z*b.z + a.w*b.w;
}

#define GEMM_SMEM (8 * 1024 * 4)

// ---------------------------------------------------------------------------
// Single-column-per-warp GEMM (q / oproj): block = 8 rows x 8 cols, warp owns
// ONE output column. 8 W chunks prefetched up-front (8 LDG.128, MLP=8, ~60
// regs -> 4 blocks/SM -> 512-block grid is a single resident wave).
// Reduce: fold 32->8 lanes (16 shfl) + distributed butterfly over 8 values
// (7 shfl); lane l<8 ends owning row l's sum.
// ---------------------------------------------------------------------------
__device__ __forceinline__ void gemm_prefetch1(
    const float* __restrict__ W, int j0, int lane, float4* wc)
{
    const float* Wp = W + (size_t)j0 * 1024 + lane * 4;
    #pragma unroll
    for (int it = 0; it < 8; it++)
        wc[it] = *(const float4*)(Wp + it * 128);
}

__device__ __forceinline__ void gemm_core1(
    const float4* wc, const float* __restrict__ bias,
    float* __restrict__ out, float scale, int row0, int j0, const float* Xs)
{
    int lane = threadIdx.x & 31;

    float acc[8];
    #pragma unroll
    for (int i = 0; i < 8; i++) acc[i] = 0.f;

    #pragma unroll
    for (int it = 0; it < 8; it++) {
        const float* xb = Xs + it * 128 + lane * 4;
        #pragma unroll
        for (int r = 0; r < 8; r++) {
            float4 x4 = *(const float4*)(xb + (r << 10));
            acc[r] += dot4(x4, wc[it]);
        }
    }

    // fold lanes: 32 -> 16 -> 8 (each lane then holds its coset sum)
    #pragma unroll
    for (int i = 0; i < 8; i++) {
        acc[i] += __shfl_xor_sync(0xffffffffu, acc[i], 16);
        acc[i] += __shfl_xor_sync(0xffffffffu, acc[i], 8);
    }
    // distributed butterfly over 8 values on lane bits 0..2
    #pragma unroll
    for (int off = 4; off; off >>= 1) {
        #pragma unroll
        for (int i = 0; i < off; i++) {
            bool hi = (lane & off) != 0;
            float z = hi ? acc[i] : acc[i + off];
            z = __shfl_xor_sync(0xffffffffu, z, off);
            acc[i] = (hi ? acc[i + off] : acc[i]) + z;
        }
    }

    if (lane < 8)
        out[(row0 + lane) * 1024 + j0] = (acc[0] + bias[j0]) * scale;
}

// Register-light GEMM for the kv branch of the fused kernel (unchanged).
__device__ __forceinline__ void gemm_compute_lite(
    const float* __restrict__ W, const float* __restrict__ bias,
    float* __restrict__ out, float scale, int row0, int colblk,
    const float* Xs)
{
    int warp = threadIdx.x >> 5;
    int lane = threadIdx.x & 31;
    int j0 = colblk * 16 + warp * 2;

    const float* Wa = W + (size_t)j0 * 1024;
    const float* Wb = Wa + 1024;

    float acc[16];
    #pragma unroll
    for (int i = 0; i < 16; i++) acc[i] = 0.f;

    float4 wa = *(const float4*)(Wa + lane * 4);
    float4 wb = *(const float4*)(Wb + lane * 4);

    #pragma unroll
    for (int it = 0; it < 8; it++) {
        int k0 = it * 128 + lane * 4;
        float4 ca = wa, cb = wb;
        if (it < 7) {
            wa = *(const float4*)(Wa + k0 + 128);
            wb = *(const float4*)(Wb + k0 + 128);
        }
        const float* xb = Xs + k0;
        #pragma unroll
        for (int r = 0; r < 8; r++) {
            float4 x4 = *(const float4*)(xb + (r << 10));
            acc[r]     += dot4(x4, ca);
            acc[8 + r] += dot4(x4, cb);
        }
    }

    #pragma unroll
    for (int i = 0; i < 16; i++)
        acc[i] += __shfl_xor_sync(0xffffffffu, acc[i], 16);
    #pragma unroll
    for (int off = 8; off; off >>= 1) {
        #pragma unroll
        for (int i = 0; i < off; i++) {
            bool hi = (lane & off) != 0;
            float z = hi ? acc[i] : acc[i + off];
            z = __shfl_xor_sync(0xffffffffu, z, off);
            acc[i] = (hi ? acc[i + off] : acc[i]) + z;
        }
    }

    if (lane < 16) {
        int c = lane >> 3, r = lane & 7;
        int j = j0 + c;
        out[(row0 + r) * 1024 + j] = (acc[0] + bias[j]) * scale;
    }
}

__device__ __forceinline__ void gemm_stage_x(const float* __restrict__ X,
                                             int row0, float* Xs)
{
    const float4* X4 = (const float4*)(X + row0 * 1024);
    float4* Xs4 = (float4*)Xs;
    for (int idx = threadIdx.x; idx < 8 * 1024 / 4; idx += 256)
        Xs4[idx] = X4[idx];
    __syncthreads();
}

// q projection (gates attention): 512 blocks = 4 row-tiles x 128 col-blocks,
// one resident wave.
__global__ __launch_bounds__(256) void q_kernel(
    const float* __restrict__ Xq, const float* __restrict__ Wq,
    const float* __restrict__ bq, float* __restrict__ oq)
{
    extern __shared__ float Xs[];
    int rt = blockIdx.x >> 7;
    int cb = blockIdx.x & 127;
    int warp = threadIdx.x >> 5;
    int lane = threadIdx.x & 31;
    int j0 = cb * 8 + warp;

    float4 wc[8];
    gemm_prefetch1(Wq, j0, lane, wc);
    gemm_stage_x(Xq, rt * 8, Xs);
    gemm_core1(wc, bq, oq, SCALING, rt * 8, j0, Xs);
}

// ---------------------------------------------------------------------------
// Fused kernel: blocks 0..511 = attention over cached positions (critical
// path); blocks 512..1023 = k/v projection GEMM backfill.  (R10 WIN config.)
// ---------------------------------------------------------------------------
__global__ __launch_bounds__(256) void attn_kv_kernel(
    const float* __restrict__ prev_key, const float* __restrict__ prev_value,
    const int*  __restrict__ order,     const int* __restrict__ mask,
    const float* __restrict__ Xk, const float* __restrict__ Xv,
    const float* __restrict__ Wk, const float* __restrict__ bk,
    const float* __restrict__ Wv, const float* __restrict__ bv,
    float* __restrict__ ok, float* __restrict__ ov)
{
    extern __shared__ float smemBuf[];

    if (blockIdx.x >= 512) {
        int blk = blockIdx.x - 512;       // p*256 + rt*64 + cb
        int p   = blk >> 8;
        int rt  = (blk >> 6) & 3;
        int cb  = blk & 63;
        if (p == 0) {
            gemm_stage_x(Xk, rt * 8, smemBuf);
            gemm_compute_lite(Wk, bk, ok, 1.0f, rt * 8, cb, smemBuf);
        } else {
            gemm_stage_x(Xv, rt * 8, smemBuf);
            gemm_compute_lite(Wv, bv, ov, 1.0f, rt * 8, cb, smemBuf);
        }
        return;
    }

    // ---- attention blocks ----
    float* s_mask = smemBuf;                       // [4096]
    float* s_m    = smemBuf + SEQ;                 // [16]
    float* s_l    = s_m + 16;                      // [16]
    float4* s_acc = (float4*)(s_l + 16);           // [16][16]

    int tid = threadIdx.x;
    int hw  = tid >> 4;
    int sl  = tid & 15;

    int n = blockIdx.x;
    int b = n >> 4;
    int h = n & 15;

    for (int idx = tid; idx < SEQ; idx += 256)
        s_mask[idx] = FLT_MAX * (float)mask[idx];
    __syncthreads();

    int ob = order[b];
    size_t cache_base = ((size_t)(ob * NUM_HEADS + h)) * PREV_LEN * HEAD_DIM;
    const float* Kc = prev_key   + cache_base;
    const float* Vc = prev_value + cache_base;

    int qbase = b * HIDDEN + h * HEAD_DIM;
    float4 q4 = *(const float4*)(g_q + qbase + sl * 4);

    float m = -FLT_MAX, l = 0.f;
    float4 acc = make_float4(0.f, 0.f, 0.f, 0.f);

    // iterations 0..254 always in bounds; deep unroll for MLP.
    #pragma unroll 8
    for (int it = 0; it < 255; it++) {
        int s = (it << 4) + hw;
        const float* kp = Kc + (size_t)s * HEAD_DIM + sl * 4;
        const float* vp = Vc + (size_t)s * HEAD_DIM + sl * 4;
        float4 k4 = *(const float4*)kp;
        float4 v4 = *(const float4*)vp;

        float p = dot4(q4, k4);
        p += __shfl_xor_sync(0xffffffffu, p, 8);
        p += __shfl_xor_sync(0xffffffffu, p, 4);
        p += __shfl_xor_sync(0xffffffffu, p, 2);
        p += __shfl_xor_sync(0xffffffffu, p, 1);

        float score = p - s_mask[s];
        float nm = fmaxf(m, score);
        float es = __expf(m - nm);
        float w  = __expf(score - nm);
        l = l * es + w;
        acc.x = acc.x * es + w * v4.x;
        acc.y = acc.y * es + w * v4.y;
        acc.z = acc.z * es + w * v4.z;
        acc.w = acc.w * es + w * v4.w;
        m = nm;
    }

    // final iteration it=255: hw==15 (s=4095) out of range; all threads run
    // the shuffles (warp-converged), invalid lanes don't accumulate.
    {
        int s = (255 << 4) + hw;
        bool valid = s < PREV_LEN;
        int sc = valid ? s : 0;
        const float* kp = Kc + (size_t)sc * HEAD_DIM + sl * 4;
        const float* vp = Vc + (size_t)sc * HEAD_DIM + sl * 4;
        float4 k4 = *(const float4*)kp;
        float4 v4 = *(const float4*)vp;

        float p = dot4(q4, k4);
        p += __shfl_xor_sync(0xffffffffu, p, 8);
        p += __shfl_xor_sync(0xffffffffu, p, 4);
        p += __shfl_xor_sync(0xffffffffu, p, 2);
        p += __shfl_xor_sync(0xffffffffu, p, 1);

        if (valid) {
            float score = p - s_mask[s];
            float nm = fmaxf(m, score);
            float es = __expf(m - nm);
            float w  = __expf(score - nm);
            l = l * es + w;
            acc.x = acc.x * es + w * v4.x;
            acc.y = acc.y * es + w * v4.y;
            acc.z = acc.z * es + w * v4.z;
            acc.w = acc.w * es + w * v4.w;
            m = nm;
        }
    }

    s_acc[hw * 16 + sl] = acc;
    if (sl == 0) { s_m[hw] = m; s_l[hw] = l; }
    __syncthreads();

    if (tid < HEAD_DIM) {
        float M = s_m[0];
        #pragma unroll
        for (int w = 1; w < 16; w++) M = fmaxf(M, s_m[w]);
        float L = 0.f, A = 0.f;
        #pragma unroll
        for (int w = 0; w < 16; w++) {
            float f = __expf(s_m[w] - M);
            L += s_l[w] * f;
            A += ((const float*)(s_acc + w * 16))[tid] * f;
        }
        g_facc[n * HEAD_DIM + tid] = A;
        if (tid == 0) { g_fm[n] = M; g_fl[n] = L; }
    }
}

// ---------------------------------------------------------------------------
// oproj + fused fresh-position merge: 512 blocks = 4 row-tiles x 128
// col-blocks, one column per warp, single resident wave.
// ---------------------------------------------------------------------------
__global__ __launch_bounds__(256) void oproj_merge_kernel(
    const int* __restrict__ mask,
    const float* __restrict__ W, const float* __restrict__ bias,
    float* __restrict__ out)
{
    extern __shared__ float Xs[];
    __shared__ float s_es[8 * 16];
    __shared__ float s_w [8 * 16];

    int rt = blockIdx.x >> 7;
    int cb = blockIdx.x & 127;
    int row0 = rt * 8;
    int tid = threadIdx.x;
    int warp = tid >> 5;
    int lane = tid & 31;
    int j0 = cb * 8 + warp;

    // W loads first — cover the merge/stage phase
    float4 wc[8];
    gemm_prefetch1(W, j0, lane, wc);

    // per-(row, head) merge coefficients (128 pairs)
    if (tid < 128) {
        int r = tid >> 4, h = tid & 15;
        int b = row0 + r;
        int n = b * NUM_HEADS + h;
        int qbase = b * HIDDEN + h * HEAD_DIM;

        float p = 0.f;
        #pragma unroll
        for (int i = 0; i < HEAD_DIM; i += 4) {
            float4 qq = *(const float4*)(g_q + qbase + i);   // pre-scaled
            float4 kk = *(const float4*)(g_k + qbase + i);
            p += dot4(qq, kk);
        }
        float score = p - FLT_MAX * (float)mask[PREV_LEN];
        float m = g_fm[n], l = g_fl[n];
        float nm = fmaxf(m, score);
        float es = __expf(m - nm);
        float w  = __expf(score - nm);
        float L  = l * es + w;
        s_es[tid] = es / L;
        s_w[tid]  = w  / L;
    }
    __syncthreads();

    // stage merged X rows: Xs[r][col] = facc*esL + v*wL
    for (int idx4 = tid; idx4 < 8 * 256; idx4 += 256) {
        int r    = idx4 >> 8;
        int c4   = idx4 & 255;
        int h    = c4 >> 4;
        int rh   = r * 16 + h;
        float esL = s_es[rh], wL = s_w[rh];
        int b = row0 + r;
        int n = b * NUM_HEADS + h;
        int d4 = c4 & 15;
        float4 fa = *(const float4*)(g_facc + n * HEAD_DIM + d4 * 4);
        float4 vv = *(const float4*)(g_v + b * HIDDEN + c4 * 4);
        float4 x;
        x.x = fa.x * esL + vv.x * wL;
        x.y = fa.y * esL + vv.y * wL;
        x.z = fa.z * esL + vv.z * wL;
        x.w = fa.w * esL + vv.w * wL;
        ((float4*)Xs)[idx4] = x;
    }
    __syncthreads();

    gemm_core1(wc, bias, out, 1.0f, row0, j0, Xs);
}

// ---------------------------------------------------------------------------
extern "C" void kernel_launch(void* const* d_in, const int* in_sizes, int n_in,
                              void* d_out, int out_size)
{
    const float* qin  = (const float*)d_in[0];
    const float* kin  = (const float*)d_in[1];
    const float* vin  = (const float*)d_in[2];
    const int*   mask = (const int*)  d_in[3];
    const int*   ord  = (const int*)  d_in[4];
    const float* pk   = (const float*)d_in[5];
    const float* pv   = (const float*)d_in[6];
    const float* Wq   = (const float*)d_in[7];
    const float* bq   = (const float*)d_in[8];
    const float* Wk   = (const float*)d_in[9];
    const float* bk   = (const float*)d_in[10];
    const float* Wv   = (const float*)d_in[11];
    const float* bv   = (const float*)d_in[12];
    const float* Wo   = (const float*)d_in[13];
    const float* bo   = (const float*)d_in[14];
    float* out = (float*)d_out;

    float *gq, *gk, *gv;
    cudaGetSymbolAddress((void**)&gq, g_q);
    cudaGetSymbolAddress((void**)&gk, g_k);
    cudaGetSymbolAddress((void**)&gv, g_v);

    q_kernel<<<512, 256, GEMM_SMEM>>>(qin, Wq, bq, gq);
    attn_kv_kernel<<<1024, 256, GEMM_SMEM>>>(pk, pv, ord, mask,
                                             kin, vin, Wk, bk, Wv, bv, gk, gv);
    oproj_merge_kernel<<<512, 256, GEMM_SMEM>>>(mask, Wo, bo, out);
}

// round 12
// speedup vs baseline: 1.0046x; 1.0046x over previous
#include <cuda_runtime.h>
#include <cuda_bf16.h>
#include <cfloat>
#include <cstdint>

#define HIDDEN    1024
#define NUM_HEADS 16
#define HEAD_DIM  64
#define BATCH     32
#define PREV_LEN  4095
#define SEQ       4096
#define SCALING   0.125f

__device__ float g_q[BATCH * HIDDEN];
__device__ float g_k[BATCH * HIDDEN];
__device__ float g_v[BATCH * HIDDEN];
// unnormalized attention partials over the 4095 cached positions
__device__ float g_fm[BATCH * NUM_HEADS];
__device__ float g_fl[BATCH * NUM_HEADS];
__device__ float g_facc[BATCH * NUM_HEADS * HEAD_DIM];

__device__ __forceinline__ float dot4(float4 a, float4 b) {
    return a.x*b.x + a.y*b.y + a.z*b.z + a.w*b.w;
}

#define GEMM_SMEM (8 * 1024 * 4)

// ---------------------------------------------------------------------------
// Deep-prefetch GEMM (R10 shape: 2 cols/warp, 16 LDG.128 up-front).
// ---------------------------------------------------------------------------
__device__ __forceinline__ void gemm_prefetch(
    const float* __restrict__ W, int j0, int lane, float4* wa, float4* wb)
{
    const float* Wa = W + (size_t)j0 * 1024 + lane * 4;
    const float* Wb = Wa + 1024;
    #pragma unroll
    for (int it = 0; it < 8; it++) {
        wa[it] = *(const float4*)(Wa + it * 128);
        wb[it] = *(const float4*)(Wb + it * 128);
    }
}

__device__ __forceinline__ void gemm_core(
    const float4* wa, const float4* wb,
    const float* __restrict__ bias, float* __restrict__ out,
    float scale, int row0, int j0, const float* Xs)
{
    int lane = threadIdx.x & 31;

    float acc[16];
    #pragma unroll
    for (int i = 0; i < 16; i++) acc[i] = 0.f;

    #pragma unroll
    for (int it = 0; it < 8; it++) {
        const float* xb = Xs + it * 128 + lane * 4;
        #pragma unroll
        for (int r = 0; r < 8; r++) {
            float4 x4 = *(const float4*)(xb + (r << 10));
            acc[r]     += dot4(x4, wa[it]);
            acc[8 + r] += dot4(x4, wb[it]);
        }
    }

    #pragma unroll
    for (int i = 0; i < 16; i++)
        acc[i] += __shfl_xor_sync(0xffffffffu, acc[i], 16);
    #pragma unroll
    for (int off = 8; off; off >>= 1) {
        #pragma unroll
        for (int i = 0; i < off; i++) {
            bool hi = (lane & off) != 0;
            float z = hi ? acc[i] : acc[i + off];
            z = __shfl_xor_sync(0xffffffffu, z, off);
            acc[i] = (hi ? acc[i + off] : acc[i]) + z;
        }
    }

    if (lane < 16) {
        int c = lane >> 3, r = lane & 7;
        int j = j0 + c;
        out[(row0 + r) * 1024 + j] = (acc[0] + bias[j]) * scale;
    }
}

// Register-light GEMM for the kv branch of the fused kernel.
__device__ __forceinline__ void gemm_compute_lite(
    const float* __restrict__ W, const float* __restrict__ bias,
    float* __restrict__ out, float scale, int row0, int colblk,
    const float* Xs)
{
    int warp = threadIdx.x >> 5;
    int lane = threadIdx.x & 31;
    int j0 = colblk * 16 + warp * 2;

    const float* Wa = W + (size_t)j0 * 1024;
    const float* Wb = Wa + 1024;

    float acc[16];
    #pragma unroll
    for (int i = 0; i < 16; i++) acc[i] = 0.f;

    float4 wa = *(const float4*)(Wa + lane * 4);
    float4 wb = *(const float4*)(Wb + lane * 4);

    #pragma unroll
    for (int it = 0; it < 8; it++) {
        int k0 = it * 128 + lane * 4;
        float4 ca = wa, cb = wb;
        if (it < 7) {
            wa = *(const float4*)(Wa + k0 + 128);
            wb = *(const float4*)(Wb + k0 + 128);
        }
        const float* xb = Xs + k0;
        #pragma unroll
        for (int r = 0; r < 8; r++) {
            float4 x4 = *(const float4*)(xb + (r << 10));
            acc[r]     += dot4(x4, ca);
            acc[8 + r] += dot4(x4, cb);
        }
    }

    #pragma unroll
    for (int i = 0; i < 16; i++)
        acc[i] += __shfl_xor_sync(0xffffffffu, acc[i], 16);
    #pragma unroll
    for (int off = 8; off; off >>= 1) {
        #pragma unroll
        for (int i = 0; i < off; i++) {
            bool hi = (lane & off) != 0;
            float z = hi ? acc[i] : acc[i + off];
            z = __shfl_xor_sync(0xffffffffu, z, off);
            acc[i] = (hi ? acc[i + off] : acc[i]) + z;
        }
    }

    if (lane < 16) {
        int c = lane >> 3, r = lane & 7;
        int j = j0 + c;
        out[(row0 + r) * 1024 + j] = (acc[0] + bias[j]) * scale;
    }
}

__device__ __forceinline__ void gemm_stage_x(const float* __restrict__ X,
                                             int row0, float* Xs)
{
    const float4* X4 = (const float4*)(X + row0 * 1024);
    float4* Xs4 = (float4*)Xs;
    for (int idx = threadIdx.x; idx < 8 * 1024 / 4; idx += 256)
        Xs4[idx] = X4[idx];
    __syncthreads();
}

// q projection (gates attention): 256 blocks (R10 shape)
__global__ __launch_bounds__(256) void q_kernel(
    const float* __restrict__ Xq, const float* __restrict__ Wq,
    const float* __restrict__ bq, float* __restrict__ oq)
{
    extern __shared__ float Xs[];
    int rt = blockIdx.x >> 6;
    int cb = blockIdx.x & 63;
    int warp = threadIdx.x >> 5;
    int lane = threadIdx.x & 31;
    int j0 = cb * 16 + warp * 2;

    float4 wa[8], wb[8];
    gemm_prefetch(Wq, j0, lane, wa, wb);
    gemm_stage_x(Xq, rt * 8, Xs);
    gemm_core(wa, wb, bq, oq, SCALING, rt * 8, j0, Xs);
}

// ---------------------------------------------------------------------------
// Fused kernel: blocks 0..511 = attention (4 positions per warp: 8-lane
// groups own a position, lane owns 8 dims). Blocks 512..1023 = kv backfill.
// ---------------------------------------------------------------------------
__global__ __launch_bounds__(256) void attn_kv_kernel(
    const float* __restrict__ prev_key, const float* __restrict__ prev_value,
    const int*  __restrict__ order,     const int* __restrict__ mask,
    const float* __restrict__ Xk, const float* __restrict__ Xv,
    const float* __restrict__ Wk, const float* __restrict__ bk,
    const float* __restrict__ Wv, const float* __restrict__ bv,
    float* __restrict__ ok, float* __restrict__ ov)
{
    extern __shared__ float smemBuf[];

    if (blockIdx.x >= 512) {
        int blk = blockIdx.x - 512;       // p*256 + rt*64 + cb
        int p   = blk >> 8;
        int rt  = (blk >> 6) & 3;
        int cb  = blk & 63;
        if (p == 0) {
            gemm_stage_x(Xk, rt * 8, smemBuf);
            gemm_compute_lite(Wk, bk, ok, 1.0f, rt * 8, cb, smemBuf);
        } else {
            gemm_stage_x(Xv, rt * 8, smemBuf);
            gemm_compute_lite(Wv, bv, ov, 1.0f, rt * 8, cb, smemBuf);
        }
        return;
    }

    // ---- attention blocks ----
    // smem: mask[4096], m[32], l[32], acc[32][64]
    float* s_mask = smemBuf;                  // 16 KB
    float* s_m    = smemBuf + SEQ;            // [32]
    float* s_l    = s_m + 32;                 // [32]
    float* s_acc  = s_l + 32;                 // [32*64] = 8 KB

    int tid  = threadIdx.x;
    int warp = tid >> 5;
    int lane = tid & 31;
    int qw   = lane >> 3;     // position-within-warp (0..3)
    int sl8  = lane & 7;      // dim-group lane (owns dims [8*sl8, 8*sl8+8))

    int n = blockIdx.x;
    int b = n >> 4;
    int h = n & 15;

    for (int idx = tid; idx < SEQ; idx += 256)
        s_mask[idx] = FLT_MAX * (float)mask[idx];
    __syncthreads();

    int ob = order[b];
    size_t cache_base = ((size_t)(ob * NUM_HEADS + h)) * PREV_LEN * HEAD_DIM;
    const float* Kc = prev_key   + cache_base;
    const float* Vc = prev_value + cache_base;

    int qbase = b * HIDDEN + h * HEAD_DIM;
    float4 qa = *(const float4*)(g_q + qbase + sl8 * 8);
    float4 qb = *(const float4*)(g_q + qbase + sl8 * 8 + 4);

    float m = -FLT_MAX, l = 0.f;
    float4 accA = make_float4(0.f, 0.f, 0.f, 0.f);
    float4 accB = make_float4(0.f, 0.f, 0.f, 0.f);

    int sbase = (warp << 2) + qw;   // this thread-group's position offset

    // iterations 0..126: s = 32*it + sbase <= 126*32+31 = 4063 < 4095.
    #pragma unroll 4
    for (int it = 0; it < 127; it++) {
        int s = (it << 5) + sbase;
        const float* kp = Kc + (size_t)s * HEAD_DIM + sl8 * 8;
        const float* vp = Vc + (size_t)s * HEAD_DIM + sl8 * 8;
        float4 ka = *(const float4*)kp;
        float4 kb = *(const float4*)(kp + 4);
        float4 va = *(const float4*)vp;
        float4 vb = *(const float4*)(vp + 4);

        float p = dot4(qa, ka) + dot4(qb, kb);
        p += __shfl_xor_sync(0xffffffffu, p, 4);
        p += __shfl_xor_sync(0xffffffffu, p, 2);
        p += __shfl_xor_sync(0xffffffffu, p, 1);

        float score = p - s_mask[s];
        float nm = fmaxf(m, score);
        float es = __expf(m - nm);
        float w  = __expf(score - nm);
        l = l * es + w;
        accA.x = accA.x * es + w * va.x;
        accA.y = accA.y * es + w * va.y;
        accA.z = accA.z * es + w * va.z;
        accA.w = accA.w * es + w * va.w;
        accB.x = accB.x * es + w * vb.x;
        accB.y = accB.y * es + w * vb.y;
        accB.z = accB.z * es + w * vb.z;
        accB.w = accB.w * es + w * vb.w;
        m = nm;
    }

    // peel it=127: s = 4064 + sbase; s==4095 (warp7,qw3) is out of range.
    // All threads execute the shuffles; invalid groups don't accumulate.
    {
        int s = (127 << 5) + sbase;
        bool valid = s < PREV_LEN;
        int sc = valid ? s : 0;
        const float* kp = Kc + (size_t)sc * HEAD_DIM + sl8 * 8;
        const float* vp = Vc + (size_t)sc * HEAD_DIM + sl8 * 8;
        float4 ka = *(const float4*)kp;
        float4 kb = *(const float4*)(kp + 4);
        float4 va = *(const float4*)vp;
        float4 vb = *(const float4*)(vp + 4);

        float p = dot4(qa, ka) + dot4(qb, kb);
        p += __shfl_xor_sync(0xffffffffu, p, 4);
        p += __shfl_xor_sync(0xffffffffu, p, 2);
        p += __shfl_xor_sync(0xffffffffu, p, 1);

        if (valid) {
            float score = p - s_mask[s];
            float nm = fmaxf(m, score);
            float es = __expf(m - nm);
            float w  = __expf(score - nm);
            l = l * es + w;
            accA.x = accA.x * es + w * va.x;
            accA.y = accA.y * es + w * va.y;
            accA.z = accA.z * es + w * va.z;
            accA.w = accA.w * es + w * va.w;
            accB.x = accB.x * es + w * vb.x;
            accB.y = accB.y * es + w * vb.y;
            accB.z = accB.z * es + w * vb.z;
            accB.w = accB.w * es + w * vb.w;
            m = nm;
        }
    }

    // epilogue: 32 groups (g = warp*4 + qw), each holding 64 dims.
    int g = sbase;                      // == warp*4 + qw
    *(float4*)(s_acc + g * 64 + sl8 * 8)     = accA;
    *(float4*)(s_acc + g * 64 + sl8 * 8 + 4) = accB;
    if (sl8 == 0) { s_m[g] = m; s_l[g] = l; }
    __syncthreads();

    if (tid < HEAD_DIM) {
        float M = s_m[0];
        #pragma unroll
        for (int w = 1; w < 32; w++) M = fmaxf(M, s_m[w]);
        float L = 0.f, A = 0.f;
        #pragma unroll
        for (int w = 0; w < 32; w++) {
            float f = __expf(s_m[w] - M);
            L += s_l[w] * f;
            A += s_acc[w * 64 + tid] * f;
        }
        g_facc[n * HEAD_DIM + tid] = A;
        if (tid == 0) { g_fm[n] = M; g_fl[n] = L; }
    }
}

// ---------------------------------------------------------------------------
// oproj + fused fresh-position merge (R10 shape).  256 blocks.
// ---------------------------------------------------------------------------
__global__ __launch_bounds__(256) void oproj_merge_kernel(
    const int* __restrict__ mask,
    const float* __restrict__ W, const float* __restrict__ bias,
    float* __restrict__ out)
{
    extern __shared__ float Xs[];
    __shared__ float s_es[8 * 16];
    __shared__ float s_w [8 * 16];

    int rt = blockIdx.x >> 6;
    int cb = blockIdx.x & 63;
    int row0 = rt * 8;
    int tid = threadIdx.x;
    int warp = tid >> 5;
    int lane = tid & 31;
    int j0 = cb * 16 + warp * 2;

    float4 wa[8], wb[8];
    gemm_prefetch(W, j0, lane, wa, wb);

    if (tid < 128) {
        int r = tid >> 4, h = tid & 15;
        int b = row0 + r;
        int n = b * NUM_HEADS + h;
        int qbase = b * HIDDEN + h * HEAD_DIM;

        float p = 0.f;
        #pragma unroll
        for (int i = 0; i < HEAD_DIM; i += 4) {
            float4 qq = *(const float4*)(g_q + qbase + i);   // pre-scaled
            float4 kk = *(const float4*)(g_k + qbase + i);
            p += dot4(qq, kk);
        }
        float score = p - FLT_MAX * (float)mask[PREV_LEN];
        float m = g_fm[n], l = g_fl[n];
        float nm = fmaxf(m, score);
        float es = __expf(m - nm);
        float w  = __expf(score - nm);
        float L  = l * es + w;
        s_es[tid] = es / L;
        s_w[tid]  = w  / L;
    }
    __syncthreads();

    for (int idx4 = tid; idx4 < 8 * 256; idx4 += 256) {
        int r    = idx4 >> 8;
        int c4   = idx4 & 255;
        int h    = c4 >> 4;
        int rh   = r * 16 + h;
        float esL = s_es[rh], wL = s_w[rh];
        int b = row0 + r;
        int n = b * NUM_HEADS + h;
        int d4 = c4 & 15;
        float4 fa = *(const float4*)(g_facc + n * HEAD_DIM + d4 * 4);
        float4 vv = *(const float4*)(g_v + b * HIDDEN + c4 * 4);
        float4 x;
        x.x = fa.x * esL + vv.x * wL;
        x.y = fa.y * esL + vv.y * wL;
        x.z = fa.z * esL + vv.z * wL;
        x.w = fa.w * esL + vv.w * wL;
        ((float4*)Xs)[idx4] = x;
    }
    __syncthreads();

    gemm_core(wa, wb, bias, out, 1.0f, row0, j0, Xs);
}

// ---------------------------------------------------------------------------
extern "C" void kernel_launch(void* const* d_in, const int* in_sizes, int n_in,
                              void* d_out, int out_size)
{
    const float* qin  = (const float*)d_in[0];
    const float* kin  = (const float*)d_in[1];
    const float* vin  = (const float*)d_in[2];
    const int*   mask = (const int*)  d_in[3];
    const int*   ord  = (const int*)  d_in[4];
    const float* pk   = (const float*)d_in[5];
    const float* pv   = (const float*)d_in[6];
    const float* Wq   = (const float*)d_in[7];
    const float* bq   = (const float*)d_in[8];
    const float* Wk   = (const float*)d_in[9];
    const float* bk   = (const float*)d_in[10];
    const float* Wv   = (const float*)d_in[11];
    const float* bv   = (const float*)d_in[12];
    const float* Wo   = (const float*)d_in[13];
    const float* bo   = (const float*)d_in[14];
    float* out = (float*)d_out;

    float *gq, *gk, *gv;
    cudaGetSymbolAddress((void**)&gq, g_q);
    cudaGetSymbolAddress((void**)&gk, g_k);
    cudaGetSymbolAddress((void**)&gv, g_v);

    q_kernel<<<256, 256, GEMM_SMEM>>>(qin, Wq, bq, gq);
    attn_kv_kernel<<<1024, 256, GEMM_SMEM>>>(pk, pv, ord, mask,
                                             kin, vin, Wk, bk, Wv, bv, gk, gv);
    oproj_merge_kernel<<<256, 256, GEMM_SMEM>>>(mask, Wo, bo, out);
}

// round 13
// speedup vs baseline: 1.0665x; 1.0616x over previous
#include <cuda_runtime.h>
#include <cuda_bf16.h>
#include <cfloat>
#include <cstdint>

#define HIDDEN    1024
#define NUM_HEADS 16
#define HEAD_DIM  64
#define BATCH     32
#define PREV_LEN  4095
#define SEQ       4096
#define SCALING   0.125f

__device__ float g_q[BATCH * HIDDEN];
__device__ float g_k[BATCH * HIDDEN];
__device__ float g_v[BATCH * HIDDEN];
// unnormalized attention partials over the 4095 cached positions
__device__ float g_fm[BATCH * NUM_HEADS];
__device__ float g_fl[BATCH * NUM_HEADS];
__device__ float g_facc[BATCH * NUM_HEADS * HEAD_DIM];

__device__ __forceinline__ float dot4(float4 a, float4 b) {
    return a.x*b.x + a.y*b.y + a.z*b.z + a.w*b.w;
}

// PDL primitives (sm_90+): trigger = allow dependents to launch (writes made
// before this are visible to dependents after their wait).
__device__ __forceinline__ void pdl_trigger() {
    asm volatile("griddepcontrol.launch_dependents;");
}
__device__ __forceinline__ void pdl_wait() {
    asm volatile("griddepcontrol.wait;");
}

#define GEMM_SMEM (8 * 1024 * 4)

// ---------------------------------------------------------------------------
// Deep-prefetch GEMM (2 cols/warp, 16 LDG.128 up-front).  R10 shape.
// ---------------------------------------------------------------------------
__device__ __forceinline__ void gemm_prefetch(
    const float* __restrict__ W, int j0, int lane, float4* wa, float4* wb)
{
    const float* Wa = W + (size_t)j0 * 1024 + lane * 4;
    const float* Wb = Wa + 1024;
    #pragma unroll
    for (int it = 0; it < 8; it++) {
        wa[it] = *(const float4*)(Wa + it * 128);
        wb[it] = *(const float4*)(Wb + it * 128);
    }
}

__device__ __forceinline__ void gemm_core(
    const float4* wa, const float4* wb,
    const float* __restrict__ bias, float* __restrict__ out,
    float scale, int row0, int j0, const float* Xs)
{
    int lane = threadIdx.x & 31;

    float acc[16];
    #pragma unroll
    for (int i = 0; i < 16; i++) acc[i] = 0.f;

    #pragma unroll
    for (int it = 0; it < 8; it++) {
        const float* xb = Xs + it * 128 + lane * 4;
        #pragma unroll
        for (int r = 0; r < 8; r++) {
            float4 x4 = *(const float4*)(xb + (r << 10));
            acc[r]     += dot4(x4, wa[it]);
            acc[8 + r] += dot4(x4, wb[it]);
        }
    }

    #pragma unroll
    for (int i = 0; i < 16; i++)
        acc[i] += __shfl_xor_sync(0xffffffffu, acc[i], 16);
    #pragma unroll
    for (int off = 8; off; off >>= 1) {
        #pragma unroll
        for (int i = 0; i < off; i++) {
            bool hi = (lane & off) != 0;
            float z = hi ? acc[i] : acc[i + off];
            z = __shfl_xor_sync(0xffffffffu, z, off);
            acc[i] = (hi ? acc[i + off] : acc[i]) + z;
        }
    }

    if (lane < 16) {
        int c = lane >> 3, r = lane & 7;
        int j = j0 + c;
        out[(row0 + r) * 1024 + j] = (acc[0] + bias[j]) * scale;
    }
}

// Register-light GEMM for the kv branch of the fused kernel.
__device__ __forceinline__ void gemm_compute_lite(
    const float* __restrict__ W, const float* __restrict__ bias,
    float* __restrict__ out, float scale, int row0, int colblk,
    const float* Xs)
{
    int warp = threadIdx.x >> 5;
    int lane = threadIdx.x & 31;
    int j0 = colblk * 16 + warp * 2;

    const float* Wa = W + (size_t)j0 * 1024;
    const float* Wb = Wa + 1024;

    float acc[16];
    #pragma unroll
    for (int i = 0; i < 16; i++) acc[i] = 0.f;

    float4 wa = *(const float4*)(Wa + lane * 4);
    float4 wb = *(const float4*)(Wb + lane * 4);

    #pragma unroll
    for (int it = 0; it < 8; it++) {
        int k0 = it * 128 + lane * 4;
        float4 ca = wa, cb = wb;
        if (it < 7) {
            wa = *(const float4*)(Wa + k0 + 128);
            wb = *(const float4*)(Wb + k0 + 128);
        }
        const float* xb = Xs + k0;
        #pragma unroll
        for (int r = 0; r < 8; r++) {
            float4 x4 = *(const float4*)(xb + (r << 10));
            acc[r]     += dot4(x4, ca);
            acc[8 + r] += dot4(x4, cb);
        }
    }

    #pragma unroll
    for (int i = 0; i < 16; i++)
        acc[i] += __shfl_xor_sync(0xffffffffu, acc[i], 16);
    #pragma unroll
    for (int off = 8; off; off >>= 1) {
        #pragma unroll
        for (int i = 0; i < off; i++) {
            bool hi = (lane & off) != 0;
            float z = hi ? acc[i] : acc[i + off];
            z = __shfl_xor_sync(0xffffffffu, z, off);
            acc[i] = (hi ? acc[i + off] : acc[i]) + z;
        }
    }

    if (lane < 16) {
        int c = lane >> 3, r = lane & 7;
        int j = j0 + c;
        out[(row0 + r) * 1024 + j] = (acc[0] + bias[j]) * scale;
    }
}

__device__ __forceinline__ void gemm_stage_x(const float* __restrict__ X,
                                             int row0, float* Xs)
{
    const float4* X4 = (const float4*)(X + row0 * 1024);
    float4* Xs4 = (float4*)Xs;
    for (int idx = threadIdx.x; idx < 8 * 1024 / 4; idx += 256)
        Xs4[idx] = X4[idx];
    __syncthreads();
}

// q projection (gates attention): 256 blocks; triggers PDL dependents after
// its stores so attn_kv schedules during q's drain.
__global__ __launch_bounds__(256) void q_kernel(
    const float* __restrict__ Xq, const float* __restrict__ Wq,
    const float* __restrict__ bq, float* __restrict__ oq)
{
    extern __shared__ float Xs[];
    int rt = blockIdx.x >> 6;
    int cb = blockIdx.x & 63;
    int warp = threadIdx.x >> 5;
    int lane = threadIdx.x & 31;
    int j0 = cb * 16 + warp * 2;

    float4 wa[8], wb[8];
    gemm_prefetch(Wq, j0, lane, wa, wb);
    gemm_stage_x(Xq, rt * 8, Xs);
    gemm_core(wa, wb, bq, oq, SCALING, rt * 8, j0, Xs);
    pdl_trigger();
}

// ---------------------------------------------------------------------------
// Fused kernel (PDL secondary of q): blocks 0..511 = attention over cached
// positions — they pre-stage the mask, then griddepcontrol.wait before
// reading g_q. Blocks 512..1023 = k/v projection backfill — independent of
// q, so they never wait and overlap q itself.
// ---------------------------------------------------------------------------
__global__ __launch_bounds__(256) void attn_kv_kernel(
    const float* __restrict__ prev_key, const float* __restrict__ prev_value,
    const int*  __restrict__ order,     const int* __restrict__ mask,
    const float* __restrict__ Xk, const float* __restrict__ Xv,
    const float* __restrict__ Wk, const float* __restrict__ bk,
    const float* __restrict__ Wv, const float* __restrict__ bv,
    float* __restrict__ ok, float* __restrict__ ov)
{
    extern __shared__ float smemBuf[];

    if (blockIdx.x >= 512) {
        int blk = blockIdx.x - 512;       // p*256 + rt*64 + cb
        int p   = blk >> 8;
        int rt  = (blk >> 6) & 3;
        int cb  = blk & 63;
        if (p == 0) {
            gemm_stage_x(Xk, rt * 8, smemBuf);
            gemm_compute_lite(Wk, bk, ok, 1.0f, rt * 8, cb, smemBuf);
        } else {
            gemm_stage_x(Xv, rt * 8, smemBuf);
            gemm_compute_lite(Wv, bv, ov, 1.0f, rt * 8, cb, smemBuf);
        }
        pdl_trigger();
        return;
    }

    // ---- attention blocks ----
    float* s_mask = smemBuf;                       // [4096]
    float* s_m    = smemBuf + SEQ;                 // [16]
    float* s_l    = s_m + 16;                      // [16]
    float4* s_acc = (float4*)(s_l + 16);           // [16][16]

    int tid = threadIdx.x;
    int hw  = tid >> 4;
    int sl  = tid & 15;

    int n = blockIdx.x;
    int b = n >> 4;
    int h = n & 15;

    // pre-sync work: mask staging + cache pointers (inputs, not q-dependent)
    for (int idx = tid; idx < SEQ; idx += 256)
        s_mask[idx] = FLT_MAX * (float)mask[idx];
    __syncthreads();

    int ob = order[b];
    size_t cache_base = ((size_t)(ob * NUM_HEADS + h)) * PREV_LEN * HEAD_DIM;
    const float* Kc = prev_key   + cache_base;
    const float* Vc = prev_value + cache_base;

    // wait for q's results before touching g_q
    pdl_wait();

    int qbase = b * HIDDEN + h * HEAD_DIM;
    float4 q4 = *(const float4*)(g_q + qbase + sl * 4);

    float m = -FLT_MAX, l = 0.f;
    float4 acc = make_float4(0.f, 0.f, 0.f, 0.f);

    // iterations 0..254 always in bounds; deep unroll for MLP.
    #pragma unroll 8
    for (int it = 0; it < 255; it++) {
        int s = (it << 4) + hw;
        const float* kp = Kc + (size_t)s * HEAD_DIM + sl * 4;
        const float* vp = Vc + (size_t)s * HEAD_DIM + sl * 4;
        float4 k4 = *(const float4*)kp;
        float4 v4 = *(const float4*)vp;

        float p = dot4(q4, k4);
        p += __shfl_xor_sync(0xffffffffu, p, 8);
        p += __shfl_xor_sync(0xffffffffu, p, 4);
        p += __shfl_xor_sync(0xffffffffu, p, 2);
        p += __shfl_xor_sync(0xffffffffu, p, 1);

        float score = p - s_mask[s];
        float nm = fmaxf(m, score);
        float es = __expf(m - nm);
        float w  = __expf(score - nm);
        l = l * es + w;
        acc.x = acc.x * es + w * v4.x;
        acc.y = acc.y * es + w * v4.y;
        acc.z = acc.z * es + w * v4.z;
        acc.w = acc.w * es + w * v4.w;
        m = nm;
    }

    // final iteration it=255: hw==15 (s=4095) out of range; all threads run
    // the shuffles (warp-converged), invalid lanes don't accumulate.
    {
        int s = (255 << 4) + hw;
        bool valid = s < PREV_LEN;
        int sc = valid ? s : 0;
        const float* kp = Kc + (size_t)sc * HEAD_DIM + sl * 4;
        const float* vp = Vc + (size_t)sc * HEAD_DIM + sl * 4;
        float4 k4 = *(const float4*)kp;
        float4 v4 = *(const float4*)vp;

        float p = dot4(q4, k4);
        p += __shfl_xor_sync(0xffffffffu, p, 8);
        p += __shfl_xor_sync(0xffffffffu, p, 4);
        p += __shfl_xor_sync(0xffffffffu, p, 2);
        p += __shfl_xor_sync(0xffffffffu, p, 1);

        if (valid) {
            float score = p - s_mask[s];
            float nm = fmaxf(m, score);
            float es = __expf(m - nm);
            float w  = __expf(score - nm);
            l = l * es + w;
            acc.x = acc.x * es + w * v4.x;
            acc.y = acc.y * es + w * v4.y;
            acc.z = acc.z * es + w * v4.z;
            acc.w = acc.w * es + w * v4.w;
            m = nm;
        }
    }

    s_acc[hw * 16 + sl] = acc;
    if (sl == 0) { s_m[hw] = m; s_l[hw] = l; }
    __syncthreads();

    if (tid < HEAD_DIM) {
        float M = s_m[0];
        #pragma unroll
        for (int w = 1; w < 16; w++) M = fmaxf(M, s_m[w]);
        float L = 0.f, A = 0.f;
        #pragma unroll
        for (int w = 0; w < 16; w++) {
            float f = __expf(s_m[w] - M);
            L += s_l[w] * f;
            A += ((const float*)(s_acc + w * 16))[tid] * f;
        }
        g_facc[n * HEAD_DIM + tid] = A;
        if (tid == 0) { g_fm[n] = M; g_fl[n] = L; }
    }
    pdl_trigger();
}

// ---------------------------------------------------------------------------
// oproj + fused fresh-position merge (PDL secondary of attn_kv): issues its
// 16-deep W prefetch BEFORE griddepcontrol.wait, hiding the entire W DRAM
// fetch under the attention tail.  256 blocks.
// ---------------------------------------------------------------------------
__global__ __launch_bounds__(256) void oproj_merge_kernel(
    const int* __restrict__ mask,
    const float* __restrict__ W, const float* __restrict__ bias,
    float* __restrict__ out)
{
    extern __shared__ float Xs[];
    __shared__ float s_es[8 * 16];
    __shared__ float s_w [8 * 16];

    int rt = blockIdx.x >> 6;
    int cb = blockIdx.x & 63;
    int row0 = rt * 8;
    int tid = threadIdx.x;
    int warp = tid >> 5;
    int lane = tid & 31;
    int j0 = cb * 16 + warp * 2;

    // W prefetch overlaps the upstream attention kernel
    float4 wa[8], wb[8];
    gemm_prefetch(W, j0, lane, wa, wb);

    // wait for attention results (g_fm/g_fl/g_facc) and kv (g_k/g_v)
    pdl_wait();

    if (tid < 128) {
        int r = tid >> 4, h = tid & 15;
        int b = row0 + r;
        int n = b * NUM_HEADS + h;
        int qbase = b * HIDDEN + h * HEAD_DIM;

        float p = 0.f;
        #pragma unroll
        for (int i = 0; i < HEAD_DIM; i += 4) {
            float4 qq = *(const float4*)(g_q + qbase + i);   // pre-scaled
            float4 kk = *(const float4*)(g_k + qbase + i);
            p += dot4(qq, kk);
        }
        float score = p - FLT_MAX * (float)mask[PREV_LEN];
        float m = g_fm[n], l = g_fl[n];
        float nm = fmaxf(m, score);
        float es = __expf(m - nm);
        float w  = __expf(score - nm);
        float L  = l * es + w;
        s_es[tid] = es / L;
        s_w[tid]  = w  / L;
    }
    __syncthreads();

    for (int idx4 = tid; idx4 < 8 * 256; idx4 += 256) {
        int r    = idx4 >> 8;
        int c4   = idx4 & 255;
        int h    = c4 >> 4;
        int rh   = r * 16 + h;
        float esL = s_es[rh], wL = s_w[rh];
        int b = row0 + r;
        int n = b * NUM_HEADS + h;
        int d4 = c4 & 15;
        float4 fa = *(const float4*)(g_facc + n * HEAD_DIM + d4 * 4);
        float4 vv = *(const float4*)(g_v + b * HIDDEN + c4 * 4);
        float4 x;
        x.x = fa.x * esL + vv.x * wL;
        x.y = fa.y * esL + vv.y * wL;
        x.z = fa.z * esL + vv.z * wL;
        x.w = fa.w * esL + vv.w * wL;
        ((float4*)Xs)[idx4] = x;
    }
    __syncthreads();

    gemm_core(wa, wb, bias, out, 1.0f, row0, j0, Xs);
}

// ---------------------------------------------------------------------------
extern "C" void kernel_launch(void* const* d_in, const int* in_sizes, int n_in,
                              void* d_out, int out_size)
{
    const float* qin  = (const float*)d_in[0];
    const float* kin  = (const float*)d_in[1];
    const float* vin  = (const float*)d_in[2];
    const int*   mask = (const int*)  d_in[3];
    const int*   ord  = (const int*)  d_in[4];
    const float* pk   = (const float*)d_in[5];
    const float* pv   = (const float*)d_in[6];
    const float* Wq   = (const float*)d_in[7];
    const float* bq   = (const float*)d_in[8];
    const float* Wk   = (const float*)d_in[9];
    const float* bk   = (const float*)d_in[10];
    const float* Wv   = (const float*)d_in[11];
    const float* bv   = (const float*)d_in[12];
    const float* Wo   = (const float*)d_in[13];
    const float* bo   = (const float*)d_in[14];
    float* out = (float*)d_out;

    float *gq, *gk, *gv;
    cudaGetSymbolAddress((void**)&gq, g_q);
    cudaGetSymbolAddress((void**)&gk, g_k);
    cudaGetSymbolAddress((void**)&gv, g_v);

    // 1) q projection (legacy default stream)
    q_kernel<<<256, 256, GEMM_SMEM>>>(qin, Wq, bq, gq);

    // 2) attn + kv, PDL-overlapped with q
    {
        cudaLaunchConfig_t cfg = {};
        cfg.gridDim  = dim3(1024, 1, 1);
        cfg.blockDim = dim3(256, 1, 1);
        cfg.dynamicSmemBytes = GEMM_SMEM;
        cfg.stream = 0;
        cudaLaunchAttribute at[1];
        at[0].id = cudaLaunchAttributeProgrammaticStreamSerialization;
        at[0].val.programmaticStreamSerializationAllowed = 1;
        cfg.attrs = at;
        cfg.numAttrs = 1;
        cudaLaunchKernelEx(&cfg, attn_kv_kernel, pk, pv, ord, mask,
                           kin, vin, Wk, bk, Wv, bv, gk, gv);
    }

    // 3) oproj + merge, PDL-overlapped with attn_kv (W prefetch pre-wait)
    {
        cudaLaunchConfig_t cfg = {};
        cfg.gridDim  = dim3(256, 1, 1);
        cfg.blockDim = dim3(256, 1, 1);
        cfg.dynamicSmemBytes = GEMM_SMEM;
        cfg.stream = 0;
        cudaLaunchAttribute at[1];
        at[0].id = cudaLaunchAttributeProgrammaticStreamSerialization;
        at[0].val.programmaticStreamSerializationAllowed = 1;
        cfg.attrs = at;
        cfg.numAttrs = 1;
        cudaLaunchKernelEx(&cfg, oproj_merge_kernel, mask, Wo, bo, out);
    }
}